// round 1
// baseline (speedup 1.0000x reference)
#include <cuda_runtime.h>
#include <math.h>

// Swin block constants
constexpr int B_   = 32;
constexpr int H_   = 56;
constexpr int W_   = 56;
constexpr int C_   = 192;
constexpr int NH_  = 6;
constexpr int WS_  = 7;
constexpr int SS_  = 3;
constexpr int N_   = 49;          // WS*WS
constexpr int HD_  = 32;          // C/NH
constexpr int NWH  = 8;           // H/WS
constexpr int NW_  = 64;          // windows per image
constexpr int HID_ = 768;         // 4*C
constexpr int TOK  = B_ * H_ * W_;   // 100352
constexpr int WINS = B_ * NW_;       // 2048
constexpr int C3   = 3 * C_;         // 576

// Scratch (device globals; no runtime allocation allowed)
__device__ float g_hwin[(size_t)TOK * C_];    // LN1 + shifted + window-partitioned
__device__ float g_qkv[(size_t)TOK * C3];     // qkv projections
__device__ float g_attno[(size_t)TOK * C_];   // attention output (window layout)
__device__ float g_x1[(size_t)TOK * C_];      // shortcut + proj (token layout)
__device__ float g_ln2[(size_t)TOK * C_];     // LN2 output
__device__ float g_hid[(size_t)TOK * HID_];   // MLP hidden

// ---------------------------------------------------------------------------
// LayerNorm. PART=1: also apply cyclic shift (-3,-3) + window partition.
// One warp per token; lane handles channels lane, lane+32, ..., lane+160.
// ---------------------------------------------------------------------------
template <int PART>
__global__ void __launch_bounds__(256) ln_kernel(
    const float* __restrict__ src, float* __restrict__ dst,
    const float* __restrict__ gamma, const float* __restrict__ beta)
{
    int warp = threadIdx.x >> 5;
    int lane = threadIdx.x & 31;
    int t = blockIdx.x * 8 + warp;
    if (t >= TOK) return;

    const float* xr = src + (size_t)t * C_;
    float v[6];
    float s = 0.f;
#pragma unroll
    for (int i = 0; i < 6; i++) { v[i] = xr[lane + 32 * i]; s += v[i]; }
#pragma unroll
    for (int o = 16; o; o >>= 1) s += __shfl_xor_sync(0xffffffffu, s, o);
    float mean = s * (1.f / 192.f);
    float ss = 0.f;
#pragma unroll
    for (int i = 0; i < 6; i++) { float d = v[i] - mean; ss += d * d; }
#pragma unroll
    for (int o = 16; o; o >>= 1) ss += __shfl_xor_sync(0xffffffffu, ss, o);
    float rstd = rsqrtf(ss * (1.f / 192.f) + 1e-5f);

    int dt = t;
    if (PART) {
        int bb = t / (H_ * W_);
        int rem = t - bb * (H_ * W_);
        int h = rem / W_, w = rem - (rem / W_) * W_;
        int hs = h - SS_; if (hs < 0) hs += H_;
        int ws = w - SS_; if (ws < 0) ws += W_;
        int wl = (hs / WS_) * NWH + (ws / WS_);
        int n  = (hs % WS_) * WS_ + (ws % WS_);
        dt = bb * (NW_ * N_) + wl * N_ + n;
    }
    float* o = dst + (size_t)dt * C_;
#pragma unroll
    for (int i = 0; i < 6; i++) {
        int c = lane + 32 * i;
        o[c] = (v[i] - mean) * rstd * gamma[c] + beta[c];
    }
}

// ---------------------------------------------------------------------------
// Tiled SGEMM: C[M,N] = A[M,K] @ B[K,N] + epilogue
//   EPI 0: + bias                             (qkv)
//   EPI 1: + bias + window-reverse/unshift scatter + residual add  (proj -> x1)
//   EPI 2: gelu(+ bias)                       (fc1)
//   EPI 3: + bias + residual add (row-major)  (fc2 -> out)
// 128x128 tile, BK=8, 8x8 per thread, 256 threads.
// ---------------------------------------------------------------------------
template <int EPI>
__global__ void __launch_bounds__(256) gemm_kernel(
    const float* __restrict__ A, const float* __restrict__ Bw,
    const float* __restrict__ bias, const float* __restrict__ add,
    float* __restrict__ Cout, int M, int N, int K)
{
    __shared__ float As[8][128];
    __shared__ float Bs[8][128];

    int tid  = threadIdx.x;
    int bm   = blockIdx.x * 128;
    int bn   = blockIdx.y * 128;
    int trow = tid >> 4;          // 0..15
    int tcol = tid & 15;          // 0..15

    float acc[8][8];
#pragma unroll
    for (int i = 0; i < 8; i++)
#pragma unroll
        for (int j = 0; j < 8; j++) acc[i][j] = 0.f;

    int aM = tid >> 1;            // 0..127
    int aK = (tid & 1) * 4;       // 0 or 4
    int bK = tid >> 5;            // 0..7
    int bN = (tid & 31) * 4;      // 0..124

    for (int k0 = 0; k0 < K; k0 += 8) {
        {
            int gm = bm + aM;
            const float* ap = A + (size_t)gm * K + (k0 + aK);
#pragma unroll
            for (int i = 0; i < 4; i++)
                As[aK + i][aM] = (gm < M) ? ap[i] : 0.f;
        }
        {
            int gn = bn + bN;
            const float* bp = Bw + (size_t)(k0 + bK) * N + gn;
#pragma unroll
            for (int i = 0; i < 4; i++)
                Bs[bK][bN + i] = (gn + i < N) ? bp[i] : 0.f;
        }
        __syncthreads();
#pragma unroll
        for (int k = 0; k < 8; k++) {
            float ra[8], rb[8];
#pragma unroll
            for (int i = 0; i < 8; i++) ra[i] = As[k][trow * 8 + i];
#pragma unroll
            for (int j = 0; j < 8; j++) rb[j] = Bs[k][tcol * 8 + j];
#pragma unroll
            for (int i = 0; i < 8; i++)
#pragma unroll
                for (int j = 0; j < 8; j++) acc[i][j] += ra[i] * rb[j];
        }
        __syncthreads();
    }

#pragma unroll
    for (int i = 0; i < 8; i++) {
        int r = bm + trow * 8 + i;
        if (r >= M) continue;
        int orow = r;
        if (EPI == 1) {
            // window-reverse + reverse cyclic shift scatter
            int win = r / N_, n = r - (r / N_) * N_;
            int b = win >> 6, wl = win & 63;
            int hs = (wl >> 3) * WS_ + n / WS_;
            int ws = (wl & 7) * WS_ + (n - (n / WS_) * WS_);
            int h = hs + SS_; if (h >= H_) h -= H_;
            int w = ws + SS_; if (w >= W_) w -= W_;
            orow = (b * H_ + h) * W_ + w;
        }
#pragma unroll
        for (int j = 0; j < 8; j++) {
            int c = bn + tcol * 8 + j;
            if (c >= N) continue;
            float v = acc[i][j] + bias[c];
            if (EPI == 1) v += add[(size_t)orow * N + c];
            if (EPI == 2) v = v * normcdff(v);
            if (EPI == 3) v += add[(size_t)r * N + c];
            Cout[(size_t)orow * N + c] = v;
        }
    }
}

// ---------------------------------------------------------------------------
// Attention: one block per (window, head). 128 threads.
// q,k,v tiles (49x32) + score matrix (49x50) in shared memory.
// ---------------------------------------------------------------------------
__global__ void __launch_bounds__(128) attn_kernel(
    const float* __restrict__ rpb, const float* __restrict__ mask)
{
    int win  = blockIdx.x;        // 0..2047
    int head = blockIdx.y;        // 0..5
    int tid  = threadIdx.x;

    __shared__ float qs[N_ * HD_];
    __shared__ float ks[N_ * HD_];
    __shared__ float vs[N_ * HD_];
    __shared__ float sc[N_ * 50];

    const float* base = g_qkv + (size_t)win * N_ * C3;
    const float scale = 0.17677669529663687f; // 1/sqrt(32)

    for (int idx = tid; idx < N_ * HD_; idx += 128) {
        int n = idx >> 5, d = idx & 31;
        const float* row = base + (size_t)n * C3 + head * HD_ + d;
        qs[idx] = row[0] * scale;
        ks[idx] = row[C_];
        vs[idx] = row[2 * C_];
    }
    __syncthreads();

    const float* mrow = mask + (size_t)(win & (NW_ - 1)) * N_ * N_;
    for (int idx = tid; idx < N_ * N_; idx += 128) {
        int n = idx / N_, m = idx - (idx / N_) * N_;
        float a = 0.f;
#pragma unroll
        for (int d = 0; d < HD_; d++) a += qs[n * HD_ + d] * ks[m * HD_ + d];
        int i1 = n / WS_, j1 = n - i1 * WS_;
        int i2 = m / WS_, j2 = m - i2 * WS_;
        int rel = (i1 - i2 + WS_ - 1) * (2 * WS_ - 1) + (j1 - j2 + WS_ - 1);
        a += rpb[rel * NH_ + head] + mrow[n * N_ + m];
        sc[n * 50 + m] = a;
    }
    __syncthreads();

    int warp = tid >> 5, lane = tid & 31;
    for (int n = warp; n < N_; n += 4) {
        float v0 = (lane < N_)      ? sc[n * 50 + lane]      : -1e30f;
        float v1 = (lane + 32 < N_) ? sc[n * 50 + lane + 32] : -1e30f;
        float mx = fmaxf(v0, v1);
#pragma unroll
        for (int o = 16; o; o >>= 1) mx = fmaxf(mx, __shfl_xor_sync(0xffffffffu, mx, o));
        float e0 = (lane < N_)      ? __expf(v0 - mx) : 0.f;
        float e1 = (lane + 32 < N_) ? __expf(v1 - mx) : 0.f;
        float s = e0 + e1;
#pragma unroll
        for (int o = 16; o; o >>= 1) s += __shfl_xor_sync(0xffffffffu, s, o);
        float inv = 1.f / s;
        if (lane < N_)      sc[n * 50 + lane]      = e0 * inv;
        if (lane + 32 < N_) sc[n * 50 + lane + 32] = e1 * inv;
    }
    __syncthreads();

    float* ob = g_attno + (size_t)win * N_ * C_ + head * HD_;
    for (int idx = tid; idx < N_ * HD_; idx += 128) {
        int n = idx >> 5, d = idx & 31;
        float a = 0.f;
#pragma unroll
        for (int m = 0; m < N_; m++) a += sc[n * 50 + m] * vs[m * HD_ + d];
        ob[(size_t)n * C_ + d] = a;
    }
}

// ---------------------------------------------------------------------------
extern "C" void kernel_launch(void* const* d_in, const int* in_sizes, int n_in,
                              void* d_out, int out_size)
{
    const float* x     = (const float*)d_in[0];
    const float* mask  = (const float*)d_in[1];
    const float* ln1g  = (const float*)d_in[2];
    const float* ln1b  = (const float*)d_in[3];
    const float* qkvw  = (const float*)d_in[4];
    const float* qkvb  = (const float*)d_in[5];
    const float* rpb   = (const float*)d_in[6];
    const float* projw = (const float*)d_in[7];
    const float* projb = (const float*)d_in[8];
    const float* ln2g  = (const float*)d_in[9];
    const float* ln2b  = (const float*)d_in[10];
    const float* fc1w  = (const float*)d_in[11];
    const float* fc1b  = (const float*)d_in[12];
    const float* fc2w  = (const float*)d_in[13];
    const float* fc2b  = (const float*)d_in[14];
    float* out = (float*)d_out;

    float *hwin, *qkv, *attno, *x1, *ln2, *hid;
    cudaGetSymbolAddress((void**)&hwin,  g_hwin);
    cudaGetSymbolAddress((void**)&qkv,   g_qkv);
    cudaGetSymbolAddress((void**)&attno, g_attno);
    cudaGetSymbolAddress((void**)&x1,    g_x1);
    cudaGetSymbolAddress((void**)&ln2,   g_ln2);
    cudaGetSymbolAddress((void**)&hid,   g_hid);

    const int ln_grid = TOK / 8;  // 12544

    // 1) LN1 + shift + window partition
    ln_kernel<1><<<ln_grid, 256>>>(x, hwin, ln1g, ln1b);

    // 2) QKV GEMM: (TOK x 192) @ (192 x 576) + bias
    gemm_kernel<0><<<dim3(TOK / 128, (C3 + 127) / 128), 256>>>(
        hwin, qkvw, qkvb, nullptr, qkv, TOK, C3, C_);

    // 3) Windowed attention
    attn_kernel<<<dim3(WINS, NH_), 128>>>(rpb, mask);

    // 4) proj GEMM + window reverse + unshift + residual -> x1
    gemm_kernel<1><<<dim3(TOK / 128, (C_ + 127) / 128), 256>>>(
        attno, projw, projb, x, x1, TOK, C_, C_);

    // 5) LN2
    ln_kernel<0><<<ln_grid, 256>>>(x1, ln2, ln2g, ln2b);

    // 6) FC1 + GELU
    gemm_kernel<2><<<dim3(TOK / 128, HID_ / 128), 256>>>(
        ln2, fc1w, fc1b, nullptr, hid, TOK, HID_, C_);

    // 7) FC2 + residual -> out
    gemm_kernel<3><<<dim3(TOK / 128, (C_ + 127) / 128), 256>>>(
        hid, fc2w, fc2b, x1, out, TOK, C_, HID_);
}

// round 3
// speedup vs baseline: 2.3289x; 2.3289x over previous
#include <cuda_runtime.h>
#include <cstdint>
#include <math.h>

// ---------------------------------------------------------------- constants
constexpr int B_   = 32;
constexpr int H_   = 56;
constexpr int W_   = 56;
constexpr int C_   = 192;
constexpr int NH_  = 6;
constexpr int WS_  = 7;
constexpr int SS_  = 3;
constexpr int N_   = 49;
constexpr int HD_  = 32;
constexpr int NWH  = 8;
constexpr int NW_  = 64;
constexpr int HID_ = 768;
constexpr int TOK  = B_ * H_ * W_;   // 100352
constexpr int WINS = B_ * NW_;       // 2048
constexpr int C3   = 3 * C_;         // 576

// GEMM tiling (mma.sync m16n8k8 tf32)
constexpr int BM = 128;
constexpr int BN = 96;
constexpr int BK = 16;
constexpr int APITCH = 20;    // floats per A smem row (BK + 4 pad)
constexpr int BPITCH = 104;   // floats per B smem row (BN + 8 pad)

// ---------------------------------------------------------------- scratch
__device__ float g_hwin[(size_t)TOK * C_];
__device__ float g_qkv[(size_t)TOK * C3];
__device__ float g_attno[(size_t)TOK * C_];
__device__ float g_x1[(size_t)TOK * C_];
__device__ float g_ln2[(size_t)TOK * C_];
__device__ float g_hid[(size_t)TOK * HID_];

// ---------------------------------------------------------------- helpers
__device__ __forceinline__ uint32_t smem_u32(const void* p) {
    uint32_t a;
    asm("{ .reg .u64 t; cvta.to.shared.u64 t, %1; cvt.u32.u64 %0, t; }"
        : "=r"(a) : "l"(p));
    return a;
}
#define CP_ASYNC16(dst_u32, src_ptr) \
    asm volatile("cp.async.ca.shared.global [%0], [%1], 16;" \
        :: "r"(dst_u32), "l"(src_ptr) : "memory")
#define CP_ASYNC_COMMIT() asm volatile("cp.async.commit_group;" ::: "memory")
#define CP_ASYNC_WAIT_1() asm volatile("cp.async.wait_group 1;" ::: "memory")
#define CP_ASYNC_WAIT_0() asm volatile("cp.async.wait_group 0;" ::: "memory")

__device__ __forceinline__ void mma_tf32(
    float* d, const uint32_t* a, const uint32_t* b)
{
    asm volatile(
        "mma.sync.aligned.m16n8k8.row.col.f32.tf32.tf32.f32 "
        "{%0,%1,%2,%3}, {%4,%5,%6,%7}, {%8,%9}, {%0,%1,%2,%3};"
        : "+f"(d[0]), "+f"(d[1]), "+f"(d[2]), "+f"(d[3])
        : "r"(a[0]), "r"(a[1]), "r"(a[2]), "r"(a[3]),
          "r"(b[0]), "r"(b[1]));
}

// ---------------------------------------------------------------- LayerNorm
template <int PART>
__global__ void __launch_bounds__(256) ln_kernel(
    const float* __restrict__ src, float* __restrict__ dst,
    const float* __restrict__ gamma, const float* __restrict__ beta)
{
    int warp = threadIdx.x >> 5;
    int lane = threadIdx.x & 31;
    int t = blockIdx.x * 8 + warp;
    if (t >= TOK) return;

    const float* xr = src + (size_t)t * C_;
    float v[6];
    float s = 0.f;
#pragma unroll
    for (int i = 0; i < 6; i++) { v[i] = xr[lane + 32 * i]; s += v[i]; }
#pragma unroll
    for (int o = 16; o; o >>= 1) s += __shfl_xor_sync(0xffffffffu, s, o);
    float mean = s * (1.f / 192.f);
    float ss = 0.f;
#pragma unroll
    for (int i = 0; i < 6; i++) { float d = v[i] - mean; ss += d * d; }
#pragma unroll
    for (int o = 16; o; o >>= 1) ss += __shfl_xor_sync(0xffffffffu, ss, o);
    float rstd = rsqrtf(ss * (1.f / 192.f) + 1e-5f);

    int dt = t;
    if (PART) {
        int bb = t / (H_ * W_);
        int rem = t - bb * (H_ * W_);
        int h = rem / W_, w = rem - (rem / W_) * W_;
        int hs = h - SS_; if (hs < 0) hs += H_;
        int ws = w - SS_; if (ws < 0) ws += W_;
        int wl = (hs / WS_) * NWH + (ws / WS_);
        int n  = (hs % WS_) * WS_ + (ws % WS_);
        dt = bb * (NW_ * N_) + wl * N_ + n;
    }
    float* o = dst + (size_t)dt * C_;
#pragma unroll
    for (int i = 0; i < 6; i++) {
        int c = lane + 32 * i;
        o[c] = (v[i] - mean) * rstd * gamma[c] + beta[c];
    }
}

// ---------------------------------------------------------------- mma GEMM
// C[M,N] = A[M,K] @ B[K,N] (B in original row-major [K][N] layout).
// 256 threads = 8 warps, warp grid 2(m) x 4(n), warp tile 64x24.
// EPI 0: +bias   EPI 1: +bias +window-reverse scatter +residual
// EPI 2: gelu(+bias)   EPI 3: +bias +residual
template <int EPI>
__global__ void __launch_bounds__(256) gemm_mma(
    const float* __restrict__ A, const float* __restrict__ Bw,
    const float* __restrict__ bias, const float* __restrict__ add,
    float* __restrict__ Cout, int M, int N, int K)
{
    __shared__ float Asb[2][BM * APITCH];   // [m][k] pitch 20
    __shared__ float Bsb[2][BK * BPITCH];   // [k][n] pitch 104

    const int tid  = threadIdx.x;
    const int wid  = tid >> 5;
    const int lane = tid & 31;
    const int wm   = wid >> 2;          // 0..1
    const int wn   = wid & 3;           // 0..3
    const int lr   = lane >> 2;         // 0..7
    const int lc   = lane & 3;          // 0..3
    const int bm   = blockIdx.x * BM;
    const int bn   = blockIdx.y * BN;
    const int nk   = K / BK;

    float acc[4][3][4];
#pragma unroll
    for (int i = 0; i < 4; i++)
#pragma unroll
        for (int j = 0; j < 3; j++)
#pragma unroll
            for (int q = 0; q < 4; q++) acc[i][j][q] = 0.f;

    uint32_t asb = smem_u32(&Asb[0][0]);
    uint32_t bsb = smem_u32(&Bsb[0][0]);

    auto load_tile = [&](int k0, int st) {
        // A: 128 rows x 16 k = 512 float4 loads
#pragma unroll
        for (int i = tid; i < 512; i += 256) {
            int m  = i >> 2;
            int k4 = i & 3;
            const float* src = A + (size_t)(bm + m) * K + k0 * BK + k4 * 4;
            uint32_t dst = asb + (uint32_t)(st * BM * APITCH + m * APITCH + k4 * 4) * 4;
            CP_ASYNC16(dst, src);
        }
        // B: 16 rows x 96 n = 384 float4 loads
#pragma unroll
        for (int i = tid; i < 384; i += 256) {
            if (i < 384) {
                int k  = i / 24;
                int n4 = i - k * 24;
                const float* src = Bw + (size_t)(k0 * BK + k) * N + bn + n4 * 4;
                uint32_t dst = bsb + (uint32_t)(st * BK * BPITCH + k * BPITCH + n4 * 4) * 4;
                CP_ASYNC16(dst, src);
            }
        }
        CP_ASYNC_COMMIT();
    };

    load_tile(0, 0);

    for (int k0 = 0; k0 < nk; k0++) {
        if (k0 + 1 < nk) { load_tile(k0 + 1, (k0 + 1) & 1); CP_ASYNC_WAIT_1(); }
        else             { CP_ASYNC_WAIT_0(); }
        __syncthreads();

        const float* As = Asb[k0 & 1];
        const float* Bs = Bsb[k0 & 1];
#pragma unroll
        for (int ks = 0; ks < 2; ks++) {
            int kk = ks * 8 + lc;
            uint32_t a[4][4];
#pragma unroll
            for (int mi = 0; mi < 4; mi++) {
                int m = wm * 64 + mi * 16 + lr;
                a[mi][0] = __float_as_uint(As[m * APITCH + kk]);
                a[mi][1] = __float_as_uint(As[(m + 8) * APITCH + kk]);
                a[mi][2] = __float_as_uint(As[m * APITCH + kk + 4]);
                a[mi][3] = __float_as_uint(As[(m + 8) * APITCH + kk + 4]);
            }
            uint32_t b[3][2];
#pragma unroll
            for (int ni = 0; ni < 3; ni++) {
                int n = wn * 24 + ni * 8 + lr;
                b[ni][0] = __float_as_uint(Bs[(ks * 8 + lc) * BPITCH + n]);
                b[ni][1] = __float_as_uint(Bs[(ks * 8 + lc + 4) * BPITCH + n]);
            }
#pragma unroll
            for (int mi = 0; mi < 4; mi++)
#pragma unroll
                for (int ni = 0; ni < 3; ni++)
                    mma_tf32(acc[mi][ni], a[mi], b[ni]);
        }
        __syncthreads();
    }

    // Epilogue: c0/c1 -> (row, 2lc), c2/c3 -> (row+8, 2lc)
#pragma unroll
    for (int mi = 0; mi < 4; mi++) {
#pragma unroll
        for (int half = 0; half < 2; half++) {
            int row = bm + wm * 64 + mi * 16 + lr + half * 8;
            int orow = row;
            if (EPI == 1) {
                int win = row / N_, n = row - win * N_;
                int b = win >> 6, wl = win & 63;
                int hs = (wl >> 3) * WS_ + n / WS_;
                int ws = (wl & 7) * WS_ + (n - (n / WS_) * WS_);
                int h = hs + SS_; if (h >= H_) h -= H_;
                int w = ws + SS_; if (w >= W_) w -= W_;
                orow = (b * H_ + h) * W_ + w;
            }
#pragma unroll
            for (int ni = 0; ni < 3; ni++) {
                int c = bn + wn * 24 + ni * 8 + 2 * lc;
                float2 bv = *(const float2*)(bias + c);
                float vx = acc[mi][ni][half * 2 + 0] + bv.x;
                float vy = acc[mi][ni][half * 2 + 1] + bv.y;
                if (EPI == 1) {
                    float2 av = *(const float2*)(add + (size_t)orow * N + c);
                    vx += av.x; vy += av.y;
                }
                if (EPI == 2) { vx *= normcdff(vx); vy *= normcdff(vy); }
                if (EPI == 3) {
                    float2 av = *(const float2*)(add + (size_t)row * N + c);
                    vx += av.x; vy += av.y;
                }
                *(float2*)(Cout + (size_t)orow * N + c) = make_float2(vx, vy);
            }
        }
    }
}

// ---------------------------------------------------------------- attention
__global__ void __launch_bounds__(128) attn_kernel(
    const float* __restrict__ rpb, const float* __restrict__ mask)
{
    int win  = blockIdx.x;
    int head = blockIdx.y;
    int tid  = threadIdx.x;

    __shared__ float qs[N_ * HD_];
    __shared__ float ks[N_ * HD_];
    __shared__ float vs[N_ * HD_];
    __shared__ float sc[N_ * 50];

    const float* base = g_qkv + (size_t)win * N_ * C3;
    const float scale = 0.17677669529663687f;

    for (int idx = tid; idx < N_ * HD_; idx += 128) {
        int n = idx >> 5, d = idx & 31;
        const float* row = base + (size_t)n * C3 + head * HD_ + d;
        qs[idx] = row[0] * scale;
        ks[idx] = row[C_];
        vs[idx] = row[2 * C_];
    }
    __syncthreads();

    const float* mrow = mask + (size_t)(win & (NW_ - 1)) * N_ * N_;
    for (int idx = tid; idx < N_ * N_; idx += 128) {
        int n = idx / N_, m = idx - (idx / N_) * N_;
        float a = 0.f;
#pragma unroll
        for (int d = 0; d < HD_; d++) a += qs[n * HD_ + d] * ks[m * HD_ + d];
        int i1 = n / WS_, j1 = n - i1 * WS_;
        int i2 = m / WS_, j2 = m - i2 * WS_;
        int rel = (i1 - i2 + WS_ - 1) * (2 * WS_ - 1) + (j1 - j2 + WS_ - 1);
        a += rpb[rel * NH_ + head] + mrow[n * N_ + m];
        sc[n * 50 + m] = a;
    }
    __syncthreads();

    int warp = tid >> 5, lane = tid & 31;
    for (int n = warp; n < N_; n += 4) {
        float v0 = (lane < N_)      ? sc[n * 50 + lane]      : -1e30f;
        float v1 = (lane + 32 < N_) ? sc[n * 50 + lane + 32] : -1e30f;
        float mx = fmaxf(v0, v1);
#pragma unroll
        for (int o = 16; o; o >>= 1) mx = fmaxf(mx, __shfl_xor_sync(0xffffffffu, mx, o));
        float e0 = (lane < N_)      ? __expf(v0 - mx) : 0.f;
        float e1 = (lane + 32 < N_) ? __expf(v1 - mx) : 0.f;
        float s = e0 + e1;
#pragma unroll
        for (int o = 16; o; o >>= 1) s += __shfl_xor_sync(0xffffffffu, s, o);
        float inv = 1.f / s;
        if (lane < N_)      sc[n * 50 + lane]      = e0 * inv;
        if (lane + 32 < N_) sc[n * 50 + lane + 32] = e1 * inv;
    }
    __syncthreads();

    float* ob = g_attno + (size_t)win * N_ * C_ + head * HD_;
    for (int idx = tid; idx < N_ * HD_; idx += 128) {
        int n = idx >> 5, d = idx & 31;
        float a = 0.f;
#pragma unroll
        for (int m = 0; m < N_; m++) a += sc[n * 50 + m] * vs[m * HD_ + d];
        ob[(size_t)n * C_ + d] = a;
    }
}

// ----------------------------------------------------------------
extern "C" void kernel_launch(void* const* d_in, const int* in_sizes, int n_in,
                              void* d_out, int out_size)
{
    const float* x     = (const float*)d_in[0];
    const float* mask  = (const float*)d_in[1];
    const float* ln1g  = (const float*)d_in[2];
    const float* ln1b  = (const float*)d_in[3];
    const float* qkvw  = (const float*)d_in[4];
    const float* qkvb  = (const float*)d_in[5];
    const float* rpb   = (const float*)d_in[6];
    const float* projw = (const float*)d_in[7];
    const float* projb = (const float*)d_in[8];
    const float* ln2g  = (const float*)d_in[9];
    const float* ln2b  = (const float*)d_in[10];
    const float* fc1w  = (const float*)d_in[11];
    const float* fc1b  = (const float*)d_in[12];
    const float* fc2w  = (const float*)d_in[13];
    const float* fc2b  = (const float*)d_in[14];
    float* out = (float*)d_out;

    float *hwin, *qkv, *attno, *x1, *ln2, *hid;
    cudaGetSymbolAddress((void**)&hwin,  g_hwin);
    cudaGetSymbolAddress((void**)&qkv,   g_qkv);
    cudaGetSymbolAddress((void**)&attno, g_attno);
    cudaGetSymbolAddress((void**)&x1,    g_x1);
    cudaGetSymbolAddress((void**)&ln2,   g_ln2);
    cudaGetSymbolAddress((void**)&hid,   g_hid);

    const int ln_grid = TOK / 8;

    // 1) LN1 + shift + window partition
    ln_kernel<1><<<ln_grid, 256>>>(x, hwin, ln1g, ln1b);

    // 2) QKV GEMM: (TOK x 192) @ (192 x 576)
    gemm_mma<0><<<dim3(TOK / BM, C3 / BN), 256>>>(
        hwin, qkvw, qkvb, nullptr, qkv, TOK, C3, C_);

    // 3) Windowed attention
    attn_kernel<<<dim3(WINS, NH_), 128>>>(rpb, mask);

    // 4) proj + window reverse + residual -> x1
    gemm_mma<1><<<dim3(TOK / BM, C_ / BN), 256>>>(
        attno, projw, projb, x, x1, TOK, C_, C_);

    // 5) LN2
    ln_kernel<0><<<ln_grid, 256>>>(x1, ln2, ln2g, ln2b);

    // 6) FC1 + GELU
    gemm_mma<2><<<dim3(TOK / BM, HID_ / BN), 256>>>(
        ln2, fc1w, fc1b, nullptr, hid, TOK, HID_, C_);

    // 7) FC2 + residual -> out
    gemm_mma<3><<<dim3(TOK / BM, C_ / BN), 256>>>(
        hid, fc2w, fc2b, x1, out, TOK, C_, HID_);
}

// round 5
// speedup vs baseline: 3.8255x; 1.6426x over previous
#include <cuda_runtime.h>
#include <cstdint>
#include <math.h>

// ---------------------------------------------------------------- constants
constexpr int B_   = 32;
constexpr int H_   = 56;
constexpr int W_   = 56;
constexpr int C_   = 192;
constexpr int NH_  = 6;
constexpr int WS_  = 7;
constexpr int SS_  = 3;
constexpr int N_   = 49;
constexpr int HD_  = 32;
constexpr int NWH  = 8;
constexpr int NW_  = 64;
constexpr int HID_ = 768;
constexpr int TOK  = B_ * H_ * W_;   // 100352
constexpr int WINS = B_ * NW_;       // 2048
constexpr int C3   = 3 * C_;         // 576

// GEMM tiling (mma.sync m16n8k8 tf32)
constexpr int BM = 128;
constexpr int BN = 96;
constexpr int BK = 16;
constexpr int APITCH = 20;    // floats per A smem row (BK + 4 pad)
constexpr int BPITCH = 104;   // floats per B smem row (BN + 8 pad)

// ---------------------------------------------------------------- scratch
__device__ float g_hwin[(size_t)TOK * C_];
__device__ float g_qkv[(size_t)TOK * C3];
__device__ float g_attno[(size_t)TOK * C_];
__device__ float g_x1[(size_t)TOK * C_];
__device__ float g_ln2[(size_t)TOK * C_];
__device__ float g_hid[(size_t)TOK * HID_];

// ---------------------------------------------------------------- helpers
__device__ __forceinline__ uint32_t smem_u32(const void* p) {
    uint32_t a;
    asm("{ .reg .u64 t; cvta.to.shared.u64 t, %1; cvt.u32.u64 %0, t; }"
        : "=r"(a) : "l"(p));
    return a;
}
#define CP_ASYNC16(dst_u32, src_ptr) \
    asm volatile("cp.async.ca.shared.global [%0], [%1], 16;" \
        :: "r"(dst_u32), "l"(src_ptr) : "memory")
#define CP_ASYNC_COMMIT() asm volatile("cp.async.commit_group;" ::: "memory")
#define CP_ASYNC_WAIT_1() asm volatile("cp.async.wait_group 1;" ::: "memory")
#define CP_ASYNC_WAIT_0() asm volatile("cp.async.wait_group 0;" ::: "memory")

__device__ __forceinline__ void mma_tf32(
    float* d, const uint32_t* a, const uint32_t* b)
{
    asm volatile(
        "mma.sync.aligned.m16n8k8.row.col.f32.tf32.tf32.f32 "
        "{%0,%1,%2,%3}, {%4,%5,%6,%7}, {%8,%9}, {%0,%1,%2,%3};"
        : "+f"(d[0]), "+f"(d[1]), "+f"(d[2]), "+f"(d[3])
        : "r"(a[0]), "r"(a[1]), "r"(a[2]), "r"(a[3]),
          "r"(b[0]), "r"(b[1]));
}

// ---------------------------------------------------------------- LayerNorm
template <int PART>
__global__ void __launch_bounds__(256) ln_kernel(
    const float* __restrict__ src, float* __restrict__ dst,
    const float* __restrict__ gamma, const float* __restrict__ beta)
{
    int warp = threadIdx.x >> 5;
    int lane = threadIdx.x & 31;
    int t = blockIdx.x * 8 + warp;
    if (t >= TOK) return;

    const float* xr = src + (size_t)t * C_;
    float v[6];
    float s = 0.f;
#pragma unroll
    for (int i = 0; i < 6; i++) { v[i] = xr[lane + 32 * i]; s += v[i]; }
#pragma unroll
    for (int o = 16; o; o >>= 1) s += __shfl_xor_sync(0xffffffffu, s, o);
    float mean = s * (1.f / 192.f);
    float ss = 0.f;
#pragma unroll
    for (int i = 0; i < 6; i++) { float d = v[i] - mean; ss += d * d; }
#pragma unroll
    for (int o = 16; o; o >>= 1) ss += __shfl_xor_sync(0xffffffffu, ss, o);
    float rstd = rsqrtf(ss * (1.f / 192.f) + 1e-5f);

    int dt = t;
    if (PART) {
        int bb = t / (H_ * W_);
        int rem = t - bb * (H_ * W_);
        int h = rem / W_, w = rem - (rem / W_) * W_;
        int hs = h - SS_; if (hs < 0) hs += H_;
        int ws = w - SS_; if (ws < 0) ws += W_;
        int wl = (hs / WS_) * NWH + (ws / WS_);
        int n  = (hs % WS_) * WS_ + (ws % WS_);
        dt = bb * (NW_ * N_) + wl * N_ + n;
    }
    float* o = dst + (size_t)dt * C_;
#pragma unroll
    for (int i = 0; i < 6; i++) {
        int c = lane + 32 * i;
        o[c] = (v[i] - mean) * rstd * gamma[c] + beta[c];
    }
}

// ---------------------------------------------------------------- mma GEMM
template <int EPI>
__global__ void __launch_bounds__(256) gemm_mma(
    const float* __restrict__ A, const float* __restrict__ Bw,
    const float* __restrict__ bias, const float* __restrict__ add,
    float* __restrict__ Cout, int M, int N, int K)
{
    __shared__ __align__(16) float Asb[2][BM * APITCH];
    __shared__ __align__(16) float Bsb[2][BK * BPITCH];

    const int tid  = threadIdx.x;
    const int wid  = tid >> 5;
    const int lane = tid & 31;
    const int wm   = wid >> 2;
    const int wn   = wid & 3;
    const int lr   = lane >> 2;
    const int lc   = lane & 3;
    const int bm   = blockIdx.x * BM;
    const int bn   = blockIdx.y * BN;
    const int nk   = K / BK;

    float acc[4][3][4];
#pragma unroll
    for (int i = 0; i < 4; i++)
#pragma unroll
        for (int j = 0; j < 3; j++)
#pragma unroll
            for (int q = 0; q < 4; q++) acc[i][j][q] = 0.f;

    uint32_t asb = smem_u32(&Asb[0][0]);
    uint32_t bsb = smem_u32(&Bsb[0][0]);

    auto load_tile = [&](int k0, int st) {
#pragma unroll
        for (int i = tid; i < 512; i += 256) {
            int m  = i >> 2;
            int k4 = i & 3;
            const float* src = A + (size_t)(bm + m) * K + k0 * BK + k4 * 4;
            uint32_t dst = asb + (uint32_t)(st * BM * APITCH + m * APITCH + k4 * 4) * 4;
            CP_ASYNC16(dst, src);
        }
#pragma unroll
        for (int i = tid; i < 384; i += 256) {
            if (i < 384) {
                int k  = i / 24;
                int n4 = i - k * 24;
                const float* src = Bw + (size_t)(k0 * BK + k) * N + bn + n4 * 4;
                uint32_t dst = bsb + (uint32_t)(st * BK * BPITCH + k * BPITCH + n4 * 4) * 4;
                CP_ASYNC16(dst, src);
            }
        }
        CP_ASYNC_COMMIT();
    };

    load_tile(0, 0);

    for (int k0 = 0; k0 < nk; k0++) {
        if (k0 + 1 < nk) { load_tile(k0 + 1, (k0 + 1) & 1); CP_ASYNC_WAIT_1(); }
        else             { CP_ASYNC_WAIT_0(); }
        __syncthreads();

        const float* As = Asb[k0 & 1];
        const float* Bs = Bsb[k0 & 1];
#pragma unroll
        for (int ks = 0; ks < 2; ks++) {
            int kk = ks * 8 + lc;
            uint32_t a[4][4];
#pragma unroll
            for (int mi = 0; mi < 4; mi++) {
                int m = wm * 64 + mi * 16 + lr;
                a[mi][0] = __float_as_uint(As[m * APITCH + kk]);
                a[mi][1] = __float_as_uint(As[(m + 8) * APITCH + kk]);
                a[mi][2] = __float_as_uint(As[m * APITCH + kk + 4]);
                a[mi][3] = __float_as_uint(As[(m + 8) * APITCH + kk + 4]);
            }
            uint32_t b[3][2];
#pragma unroll
            for (int ni = 0; ni < 3; ni++) {
                int n = wn * 24 + ni * 8 + lr;
                b[ni][0] = __float_as_uint(Bs[(ks * 8 + lc) * BPITCH + n]);
                b[ni][1] = __float_as_uint(Bs[(ks * 8 + lc + 4) * BPITCH + n]);
            }
#pragma unroll
            for (int mi = 0; mi < 4; mi++)
#pragma unroll
                for (int ni = 0; ni < 3; ni++)
                    mma_tf32(acc[mi][ni], a[mi], b[ni]);
        }
        __syncthreads();
    }

#pragma unroll
    for (int mi = 0; mi < 4; mi++) {
#pragma unroll
        for (int half = 0; half < 2; half++) {
            int row = bm + wm * 64 + mi * 16 + lr + half * 8;
            int orow = row;
            if (EPI == 1) {
                int win = row / N_, n = row - win * N_;
                int b = win >> 6, wl = win & 63;
                int hs = (wl >> 3) * WS_ + n / WS_;
                int ws = (wl & 7) * WS_ + (n - (n / WS_) * WS_);
                int h = hs + SS_; if (h >= H_) h -= H_;
                int w = ws + SS_; if (w >= W_) w -= W_;
                orow = (b * H_ + h) * W_ + w;
            }
#pragma unroll
            for (int ni = 0; ni < 3; ni++) {
                int c = bn + wn * 24 + ni * 8 + 2 * lc;
                float2 bv = *(const float2*)(bias + c);
                float vx = acc[mi][ni][half * 2 + 0] + bv.x;
                float vy = acc[mi][ni][half * 2 + 1] + bv.y;
                if (EPI == 1) {
                    float2 av = *(const float2*)(add + (size_t)orow * N + c);
                    vx += av.x; vy += av.y;
                }
                if (EPI == 2) { vx *= normcdff(vx); vy *= normcdff(vy); }
                if (EPI == 3) {
                    float2 av = *(const float2*)(add + (size_t)row * N + c);
                    vx += av.x; vy += av.y;
                }
                *(float2*)(Cout + (size_t)orow * N + c) = make_float2(vx, vy);
            }
        }
    }
}

// ---------------------------------------------------------------- attention
// One block per (window, head), 128 threads. Register-blocked, broadcast-
// friendly smem access. All vector-accessed shared arrays are 16B-aligned
// (the R4 crash was vs[] landing at offset 8 mod 16).
__global__ void __launch_bounds__(128) attn_kernel(
    const float* __restrict__ rpb, const float* __restrict__ mask)
{
    int win  = blockIdx.x;
    int head = blockIdx.y;
    int tid  = threadIdx.x;

    __shared__ __align__(16) float qs[N_][34];   // pitch 34
    __shared__ __align__(16) float kT[HD_][50];  // transposed K, pitch 50
    __shared__ __align__(16) float vs[N_][HD_];  // pitch 32 (float4 accessed)
    __shared__ __align__(16) float sc[N_][50];   // scores, pitch 50
    __shared__ __align__(16) float rpbs[169];    // staged RPB

    const float* base = g_qkv + (size_t)win * N_ * C3 + head * HD_;
    const float scale = 0.17677669529663687f;

    for (int idx = tid; idx < N_ * HD_; idx += 128) {
        int n = idx >> 5, d = idx & 31;
        const float* row = base + (size_t)n * C3 + d;
        qs[n][d] = row[0] * scale;
        kT[d][n] = row[C_];
        vs[n][d] = row[2 * C_];
    }
    for (int idx = tid; idx < 169; idx += 128)
        rpbs[idx] = rpb[idx * NH_ + head];
    __syncthreads();

    // ---- scores: cells = (n-group of 7) x (m-pair). 7*25 = 175 cells.
    const float* mrow = mask + (size_t)(win & (NW_ - 1)) * N_ * N_;
    for (int cell = tid; cell < 175; cell += 128) {
        int ng = cell / 25;
        int m2 = cell - ng * 25;
        int m  = m2 * 2;
        float acc[7][2];
#pragma unroll
        for (int j = 0; j < 7; j++) { acc[j][0] = 0.f; acc[j][1] = 0.f; }
#pragma unroll
        for (int d = 0; d < HD_; d += 2) {
            float2 k0 = *(const float2*)&kT[d][m];       // (k[m][d],   k[m+1][d])
            float2 k1 = *(const float2*)&kT[d + 1][m];   // (k[m][d+1], k[m+1][d+1])
#pragma unroll
            for (int j = 0; j < 7; j++) {
                float2 qv = *(const float2*)&qs[ng * 7 + j][d];
                acc[j][0] += qv.x * k0.x + qv.y * k1.x;
                acc[j][1] += qv.x * k0.y + qv.y * k1.y;
            }
        }
        int i2 = m / WS_, j2 = m - i2 * WS_;
        int i2b = (m + 1) / WS_, j2b = (m + 1) - i2b * WS_;
#pragma unroll
        for (int j = 0; j < 7; j++) {
            int n = ng * 7 + j;
            int i1 = n / WS_, j1 = n - i1 * WS_;
            int rel0 = (i1 - i2 + WS_ - 1) * (2 * WS_ - 1) + (j1 - j2 + WS_ - 1);
            sc[n][m] = acc[j][0] + rpbs[rel0] + mrow[n * N_ + m];
            if (m + 1 < N_) {
                int rel1 = (i1 - i2b + WS_ - 1) * (2 * WS_ - 1) + (j1 - j2b + WS_ - 1);
                sc[n][m + 1] = acc[j][1] + rpbs[rel1] + mrow[n * N_ + m + 1];
            }
        }
    }
    __syncthreads();

    // ---- softmax (rowwise over 49)
    int warp = tid >> 5, lane = tid & 31;
    for (int n = warp; n < N_; n += 4) {
        float v0 = (lane < N_)      ? sc[n][lane]      : -1e30f;
        float v1 = (lane + 32 < N_) ? sc[n][lane + 32] : -1e30f;
        float mx = fmaxf(v0, v1);
#pragma unroll
        for (int o = 16; o; o >>= 1) mx = fmaxf(mx, __shfl_xor_sync(0xffffffffu, mx, o));
        float e0 = (lane < N_)      ? __expf(v0 - mx) : 0.f;
        float e1 = (lane + 32 < N_) ? __expf(v1 - mx) : 0.f;
        float s = e0 + e1;
#pragma unroll
        for (int o = 16; o; o >>= 1) s += __shfl_xor_sync(0xffffffffu, s, o);
        float inv = 1.f / s;
        if (lane < N_)      sc[n][lane]      = e0 * inv;
        if (lane + 32 < N_) sc[n][lane + 32] = e1 * inv;
    }
    __syncthreads();

    // ---- PV: cells = (n-block of 4) x (d-block of 4). 13*8 = 104 cells.
    if (tid < 104) {
        int ngb = tid >> 3;
        int d   = (tid & 7) * 4;
        float acc[4][4];
#pragma unroll
        for (int i = 0; i < 4; i++)
#pragma unroll
            for (int q = 0; q < 4; q++) acc[i][q] = 0.f;

        for (int m = 0; m < N_; m++) {
            float4 vv = *(const float4*)&vs[m][d];
#pragma unroll
            for (int i = 0; i < 4; i++) {
                int n = ngb * 4 + i;
                float p = (n < N_) ? sc[n][m] : 0.f;
                acc[i][0] += p * vv.x;
                acc[i][1] += p * vv.y;
                acc[i][2] += p * vv.z;
                acc[i][3] += p * vv.w;
            }
        }
        float* ob = g_attno + (size_t)win * N_ * C_ + head * HD_;
#pragma unroll
        for (int i = 0; i < 4; i++) {
            int n = ngb * 4 + i;
            if (n < N_)
                *(float4*)(ob + (size_t)n * C_ + d) =
                    make_float4(acc[i][0], acc[i][1], acc[i][2], acc[i][3]);
        }
    }
}

// ----------------------------------------------------------------
extern "C" void kernel_launch(void* const* d_in, const int* in_sizes, int n_in,
                              void* d_out, int out_size)
{
    const float* x     = (const float*)d_in[0];
    const float* mask  = (const float*)d_in[1];
    const float* ln1g  = (const float*)d_in[2];
    const float* ln1b  = (const float*)d_in[3];
    const float* qkvw  = (const float*)d_in[4];
    const float* qkvb  = (const float*)d_in[5];
    const float* rpb   = (const float*)d_in[6];
    const float* projw = (const float*)d_in[7];
    const float* projb = (const float*)d_in[8];
    const float* ln2g  = (const float*)d_in[9];
    const float* ln2b  = (const float*)d_in[10];
    const float* fc1w  = (const float*)d_in[11];
    const float* fc1b  = (const float*)d_in[12];
    const float* fc2w  = (const float*)d_in[13];
    const float* fc2b  = (const float*)d_in[14];
    float* out = (float*)d_out;

    float *hwin, *qkv, *attno, *x1, *ln2, *hid;
    cudaGetSymbolAddress((void**)&hwin,  g_hwin);
    cudaGetSymbolAddress((void**)&qkv,   g_qkv);
    cudaGetSymbolAddress((void**)&attno, g_attno);
    cudaGetSymbolAddress((void**)&x1,    g_x1);
    cudaGetSymbolAddress((void**)&ln2,   g_ln2);
    cudaGetSymbolAddress((void**)&hid,   g_hid);

    const int ln_grid = TOK / 8;

    // 1) LN1 + shift + window partition
    ln_kernel<1><<<ln_grid, 256>>>(x, hwin, ln1g, ln1b);

    // 2) QKV GEMM
    gemm_mma<0><<<dim3(TOK / BM, C3 / BN), 256>>>(
        hwin, qkvw, qkvb, nullptr, qkv, TOK, C3, C_);

    // 3) Windowed attention
    attn_kernel<<<dim3(WINS, NH_), 128>>>(rpb, mask);

    // 4) proj + window reverse + residual -> x1
    gemm_mma<1><<<dim3(TOK / BM, C_ / BN), 256>>>(
        attno, projw, projb, x, x1, TOK, C_, C_);

    // 5) LN2
    ln_kernel<0><<<ln_grid, 256>>>(x1, ln2, ln2g, ln2b);

    // 6) FC1 + GELU
    gemm_mma<2><<<dim3(TOK / BM, HID_ / BN), 256>>>(
        ln2, fc1w, fc1b, nullptr, hid, TOK, HID_, C_);

    // 7) FC2 + residual -> out
    gemm_mma<3><<<dim3(TOK / BM, C_ / BN), 256>>>(
        hid, fc2w, fc2b, x1, out, TOK, C_, HID_);
}